// round 15
// baseline (speedup 1.0000x reference)
#include <cuda_runtime.h>
#include <math.h>

#define NE     8
#define NB     100000
#define DIM    1024
#define NSUP   128
#define KSEL   15000u
#define MAXC   8192
#define HB     8192         // 13-bit histogram bins
#define HSHIFT 19           // key >> 19 = 13-bit prefix

// ---------------- scratch ----------------
__device__ float    g_q[NE][DIM];
__device__ float    g_sim[NE * NB];
__device__ float    g_invnorm[NB];
__device__ unsigned g_h1[NE][HB];
__device__ unsigned g_bin13[NE];
__device__ unsigned g_rank[NE];
__device__ int      g_cand[NE][MAXC];
__device__ int      g_ccnt[NE];
__device__ unsigned g_thr_key[NE];
__device__ int      g_tiecut[NE];
__device__ float    g_approx[NE][DIM];

__device__ __forceinline__ unsigned tokey(float f) {
    unsigned b = __float_as_uint(f);
    return b ^ ((unsigned)((int)b >> 31) | 0x80000000u);
}

// ---------------- init ----------------
__global__ void kInit() {
    unsigned i = blockIdx.x * blockDim.x + threadIdx.x;
    unsigned stride = gridDim.x * blockDim.x;
    unsigned* h1 = &g_h1[0][0];
    for (unsigned k = i; k < NE * HB; k += stride) h1[k] = 0u;
    float* ap = &g_approx[0][0];
    for (unsigned k = i; k < NE * DIM; k += stride) ap[k] = 0.0f;
    float* qq = &g_q[0][0];
    for (unsigned k = i; k < NE * DIM; k += stride) qq[k] = 0.0f;
    if (i < NE) g_ccnt[i] = 0;
}

// ---------------- A: support mean, 4 blocks per episode ----------------
__global__ void __launch_bounds__(1024) kA(const float* __restrict__ feats) {
    int e = blockIdx.x, chunk = blockIdx.y;
    int tid = threadIdx.x, lane = tid & 31, wid = tid >> 5;
    __shared__ float s_inv[32];
    const float* fe = feats + (size_t)e * DIM * DIM + (size_t)chunk * 32 * DIM;
    {
        const float4* row4 = (const float4*)(fe + (size_t)wid * DIM);
        float s = 0.f;
        #pragma unroll
        for (int k = 0; k < 8; k++) {
            float4 v = row4[k * 32 + lane];
            s += v.x * v.x + v.y * v.y + v.z * v.z + v.w * v.w;
        }
        #pragma unroll
        for (int o = 16; o > 0; o >>= 1) s += __shfl_xor_sync(0xFFFFFFFFu, s, o);
        if (lane == 0) s_inv[wid] = rsqrtf(fmaxf(s, 1e-24f));
    }
    __syncthreads();
    float acc = 0.f;
    #pragma unroll 8
    for (int r = 0; r < 32; r++) acc += fe[(size_t)r * DIM + tid] * s_inv[r];
    atomicAdd(&g_q[e][tid], acc);
}

// ---------------- B: sims (FROZEN 92us version — 4 rows/warp) ----------------
__global__ void __launch_bounds__(128) kB(const float* __restrict__ base) {
    __shared__ float4 sq[NE * 256];   // 32 KB
    for (int i = threadIdx.x; i < NE * 256; i += 128) sq[i] = ((const float4*)g_q)[i];
    __syncthreads();
    int lane = threadIdx.x & 31;
    int gw = (blockIdx.x * 128 + threadIdx.x) >> 5;
    int nw = (gridDim.x * 128) >> 5;
    for (int g = gw; g < NB / 4; g += nw) {
        const float4* p0 = (const float4*)(base + (size_t)(4 * g) * DIM);
        const float4* p1 = p0 + 256;
        const float4* p2 = p0 + 512;
        const float4* p3 = p0 + 768;
        float acc[4][8];
        float ss[4];
        #pragma unroll
        for (int r = 0; r < 4; r++) {
            ss[r] = 0.f;
            #pragma unroll
            for (int e = 0; e < 8; e++) acc[r][e] = 0.f;
        }
        #pragma unroll 2
        for (int k = 0; k < 8; k++) {
            float4 v0 = p0[k * 32 + lane];
            float4 v1 = p1[k * 32 + lane];
            float4 v2 = p2[k * 32 + lane];
            float4 v3 = p3[k * 32 + lane];
            ss[0] += v0.x * v0.x + v0.y * v0.y + v0.z * v0.z + v0.w * v0.w;
            ss[1] += v1.x * v1.x + v1.y * v1.y + v1.z * v1.z + v1.w * v1.w;
            ss[2] += v2.x * v2.x + v2.y * v2.y + v2.z * v2.z + v2.w * v2.w;
            ss[3] += v3.x * v3.x + v3.y * v3.y + v3.z * v3.z + v3.w * v3.w;
            #pragma unroll
            for (int e = 0; e < 8; e++) {
                float4 q = sq[e * 256 + k * 32 + lane];
                acc[0][e] += v0.x * q.x + v0.y * q.y + v0.z * q.z + v0.w * q.w;
                acc[1][e] += v1.x * q.x + v1.y * q.y + v1.z * q.z + v1.w * q.w;
                acc[2][e] += v2.x * q.x + v2.y * q.y + v2.z * q.z + v2.w * q.w;
                acc[3][e] += v3.x * q.x + v3.y * q.y + v3.z * q.z + v3.w * q.w;
            }
        }
        #pragma unroll
        for (int r = 0; r < 4; r++) {
            float s = ss[r];
            #pragma unroll
            for (int o = 16; o > 0; o >>= 1) s += __shfl_xor_sync(0xFFFFFFFFu, s, o);
            float inv = rsqrtf(fmaxf(s, 1e-24f));
            if (lane == 0) g_invnorm[4 * g + r] = inv;
            #pragma unroll
            for (int e = 0; e < 8; e++) {
                float d = acc[r][e];
                #pragma unroll
                for (int o = 16; o > 0; o >>= 1) d += __shfl_xor_sync(0xFFFFFFFFu, d, o);
                if (lane == 0) g_sim[e * NB + 4 * g + r] = d * inv;
            }
        }
    }
}

// ---------------- H1: 13-bit histogram, float4 sweep ----------------
__global__ void __launch_bounds__(1024) kH1() {
    int e = blockIdx.y;
    __shared__ unsigned h[HB];        // 32 KB
    int t = threadIdx.x;
    #pragma unroll
    for (int j = 0; j < HB / 1024; j++) h[t + j * 1024] = 0u;
    __syncthreads();
    const float4* s4 = (const float4*)(g_sim + (size_t)e * NB);
    int i0 = blockIdx.x * 2048 + t;
    #pragma unroll
    for (int rr = 0; rr < 2; rr++) {
        int i = i0 + rr * 1024;
        if (i < NB / 4) {
            float4 v = s4[i];
            atomicAdd(&h[tokey(v.x) >> HSHIFT], 1u);
            atomicAdd(&h[tokey(v.y) >> HSHIFT], 1u);
            atomicAdd(&h[tokey(v.z) >> HSHIFT], 1u);
            atomicAdd(&h[tokey(v.w) >> HSHIFT], 1u);
        }
    }
    __syncthreads();
    #pragma unroll
    for (int j = 0; j < HB / 1024; j++) {
        unsigned c = h[t + j * 1024];
        if (c) atomicAdd(&g_h1[e][t + j * 1024], c);
    }
}

// ---------------- Find: K-th bin + within-bin rank over 8192 bins ----------------
__global__ void __launch_bounds__(1024) kFind() {
    int e = blockIdx.x;
    const unsigned* hist = g_h1[e];
    int t = threadIdx.x, lane = t & 31, wid = t >> 5;
    unsigned base = (unsigned)t * (HB / 1024);
    unsigned part = 0;
    unsigned hb[8];
    #pragma unroll
    for (int j = 0; j < 8; j++) { hb[j] = hist[base + j]; part += hb[j]; }
    unsigned x = part;
    #pragma unroll
    for (int o = 1; o < 32; o <<= 1) { unsigned y = __shfl_up_sync(0xFFFFFFFFu, x, o); if (lane >= o) x += y; }
    __shared__ unsigned s_ws[32];
    __shared__ unsigned s_total;
    if (lane == 31) s_ws[wid] = x;
    __syncthreads();
    if (wid == 0) {
        unsigned w = s_ws[lane];
        #pragma unroll
        for (int o = 1; o < 32; o <<= 1) { unsigned y = __shfl_up_sync(0xFFFFFFFFu, w, o); if (lane >= o) w += y; }
        s_ws[lane] = w;
        if (lane == 31) s_total = w;
    }
    __syncthreads();
    unsigned incl = x + (wid ? s_ws[wid - 1] : 0u);
    unsigned above = s_total - incl;
    if (above < KSEL && KSEL <= above + part) {
        unsigned cum = above;
        for (int j = 7; j >= 0; j--) {
            unsigned c = hb[j];
            if (cum + c >= KSEL) { g_bin13[e] = base + j; g_rank[e] = KSEL - cum; break; }
            cum += c;
        }
    }
}

// ---------------- Cand: float4 sweep, collect 13-bit-prefix matches ----------------
__global__ void __launch_bounds__(1024) kCand() {
    int e = blockIdx.y;
    unsigned bin = g_bin13[e];
    const float4* s4 = (const float4*)(g_sim + (size_t)e * NB);
    int i0 = blockIdx.x * 2048 + threadIdx.x;
    #pragma unroll
    for (int rr = 0; rr < 2; rr++) {
        int i = i0 + rr * 1024;
        if (i < NB / 4) {
            float4 v = s4[i];
            float sv[4] = {v.x, v.y, v.z, v.w};
            #pragma unroll
            for (int j = 0; j < 4; j++) {
                if ((tokey(sv[j]) >> HSHIFT) == bin) {
                    int p = atomicAdd(&g_ccnt[e], 1);
                    if (p < MAXC) g_cand[e][p] = 4 * i + j;
                }
            }
        }
    }
}

// ---------------- Resolve v2: two-level O(cnt) rank resolve ----------------
__global__ void __launch_bounds__(1024) kResolve() {
    int e = blockIdx.x;
    int cnt = min(g_ccnt[e], MAXC);
    unsigned rank = g_rank[e];
    int t = threadIdx.x;
    const float* sims = g_sim + (size_t)e * NB;
    const int* cand = g_cand[e];

    __shared__ unsigned h[256], sfx[256];
    __shared__ unsigned s_bin, s_rank2;
    __shared__ int s_m;
    __shared__ int midx[1024];
    __shared__ unsigned mkey[1024];
    if (t < 256) { h[t] = 0u; }
    if (t == 0) s_m = 0;
    __syncthreads();
    for (int i = t; i < cnt; i += 1024) {
        unsigned key = tokey(sims[cand[i]]);
        atomicAdd(&h[(key >> 11) & 0xFFu], 1u);
    }
    __syncthreads();
    if (t < 256) sfx[t] = h[t];
    __syncthreads();
    #pragma unroll
    for (int o = 1; o < 256; o <<= 1) {
        unsigned v = 0;
        if (t < 256 && t + o < 256) v = sfx[t + o];
        __syncthreads();
        if (t < 256) sfx[t] += v;
        __syncthreads();
    }
    if (t < 256) {
        unsigned tot = sfx[t], above = tot - h[t];
        if (above < rank && rank <= tot) { s_bin = (unsigned)t; s_rank2 = rank - above; }
    }
    __syncthreads();
    unsigned b = s_bin, rank2 = s_rank2;

    for (int i = t; i < cnt; i += 1024) {
        int idx = cand[i];
        unsigned key = tokey(sims[idx]);
        if (((key >> 11) & 0xFFu) == b) {
            int p = atomicAdd(&s_m, 1);
            if (p < 1024) { midx[p] = idx; mkey[p] = key; }
        }
    }
    __syncthreads();
    int m = min(s_m, 1024);
    for (int i = t; i < m; i += 1024) {
        int my = midx[i]; unsigned myk = mkey[i];
        int r = 0;
        for (int j = 0; j < m; j++) {
            unsigned ok = mkey[j]; int oj = midx[j];
            r += (ok > myk) || (ok == myk && oj < my);
        }
        if (r == (int)rank2 - 1) { g_thr_key[e] = myk; g_tiecut[e] = my; }
    }
}

// ---------------- D: warp-per-episode sparse weighted accumulation ----------------
__global__ void __launch_bounds__(256) kD(const float* __restrict__ base) {
    int e = threadIdx.x >> 5;
    int lane = threadIdx.x & 31;
    unsigned thr = g_thr_key[e];
    int cut = g_tiecut[e];
    const float* sims = g_sim + (size_t)e * NB;
    const float4* b4 = (const float4*)base;
    float4 acc[8];
    #pragma unroll
    for (int i = 0; i < 8; i++) acc[i] = make_float4(0.f, 0.f, 0.f, 0.f);
    for (int tile = blockIdx.x; tile < NB / 16; tile += gridDim.x) {
        int row0 = tile * 16;
        float w = 0.f;
        if (lane < 16) {
            int row = row0 + lane;
            float sim = sims[row];
            unsigned key = tokey(sim);
            bool sel = (key > thr) || (key == thr && row <= cut);
            w = sel ? (sqrtf(fmaxf(sim, 0.f)) * g_invnorm[row]) : 0.f;
        }
        unsigned mask = __ballot_sync(0xFFFFFFFFu, w != 0.f);
        while (mask) {
            int r = __ffs(mask) - 1; mask &= mask - 1;
            float wr = __shfl_sync(0xFFFFFFFFu, w, r);
            const float4* rp = b4 + (size_t)(row0 + r) * 256;
            #pragma unroll
            for (int i = 0; i < 8; i++) {
                float4 v = rp[i * 32 + lane];
                acc[i].x += wr * v.x; acc[i].y += wr * v.y;
                acc[i].z += wr * v.z; acc[i].w += wr * v.w;
            }
        }
    }
    #pragma unroll
    for (int i = 0; i < 8; i++) {
        int c = (i * 32 + lane) * 4;
        atomicAdd(&g_approx[e][c + 0], acc[i].x);
        atomicAdd(&g_approx[e][c + 1], acc[i].y);
        atomicAdd(&g_approx[e][c + 2], acc[i].z);
        atomicAdd(&g_approx[e][c + 3], acc[i].w);
    }
}

// ---------------- F: orthogonalize (approx normalization fused in) ----------------
__global__ void __launch_bounds__(256) kF(const float* __restrict__ feats, float* __restrict__ out) {
    int b = blockIdx.x;
    int e = b >> 7;
    int tid = threadIdx.x;
    int lane = tid & 31, warp = tid >> 5;

    __shared__ float s_part[8];
    __shared__ float s_inva;
    const float4* a4 = (const float4*)g_approx[e];
    {
        float4 av = a4[tid];
        float ss = av.x * av.x + av.y * av.y + av.z * av.z + av.w * av.w;
        #pragma unroll
        for (int o = 16; o > 0; o >>= 1) ss += __shfl_xor_sync(0xFFFFFFFFu, ss, o);
        if (lane == 0) s_part[warp] = ss;
    }
    __syncthreads();
    if (tid == 0) {
        float tsum = 0.f;
        #pragma unroll
        for (int i = 0; i < 8; i++) tsum += s_part[i];
        s_inva = rsqrtf(fmaxf(tsum, 1e-24f));
    }
    __syncthreads();
    float inva = s_inva;

    int rowInEp = (b & 127) * 8 + warp;
    size_t off = ((size_t)e * DIM + rowInEp) * DIM;
    const float4* f4 = (const float4*)(feats + off);
    float4* o4 = (float4*)(out + off);
    float4 v[8], a[8];
    float ss = 0.f, dd = 0.f;
    #pragma unroll
    for (int k = 0; k < 8; k++) {
        v[k] = f4[k * 32 + lane];
        a[k] = a4[k * 32 + lane];
        ss += v[k].x * v[k].x + v[k].y * v[k].y + v[k].z * v[k].z + v[k].w * v[k].w;
        dd += v[k].x * a[k].x + v[k].y * a[k].y + v[k].z * a[k].z + v[k].w * a[k].w;
    }
    #pragma unroll
    for (int o = 16; o > 0; o >>= 1) {
        ss += __shfl_xor_sync(0xFFFFFFFFu, ss, o);
        dd += __shfl_xor_sync(0xFFFFFFFFu, dd, o);
    }
    float invf = rsqrtf(fmaxf(ss, 1e-24f));
    float c = dd * invf * inva;
    float tcoef = c * inva;
    float sc = rsqrtf(fmaxf(1.0f - c * c, 1e-24f));
    #pragma unroll
    for (int k = 0; k < 8; k++) {
        float4 r;
        r.x = (v[k].x * invf - tcoef * a[k].x) * sc;
        r.y = (v[k].y * invf - tcoef * a[k].y) * sc;
        r.z = (v[k].z * invf - tcoef * a[k].z) * sc;
        r.w = (v[k].w * invf - tcoef * a[k].w) * sc;
        o4[k * 32 + lane] = r;
    }
}

// ---------------- launch ----------------
extern "C" void kernel_launch(void* const* d_in, const int* in_sizes, int n_in,
                              void* d_out, int out_size) {
    const float* feats = (const float*)d_in[0];
    const float* base  = (const float*)d_in[1];
    float* out = (float*)d_out;
    (void)in_sizes; (void)n_in; (void)out_size;

    kInit<<<64, 1024>>>();
    kA<<<dim3(NE, 4), 1024>>>(feats);
    kB<<<1480, 128>>>(base);
    kH1<<<dim3(13, NE), 1024>>>();     // 13*2048 >= 25000 float4
    kFind<<<NE, 1024>>>();
    kCand<<<dim3(13, NE), 1024>>>();
    kResolve<<<NE, 1024>>>();
    kD<<<592, 256>>>(base);
    kF<<<1024, 256>>>(feats, out);
}

// round 16
// speedup vs baseline: 1.1065x; 1.1065x over previous
#include <cuda_runtime.h>
#include <math.h>

#define NE     8
#define NB     100000
#define DIM    1024
#define NSUP   128
#define KSEL   15000u
#define MAXC   8192
#define HB     8192         // 13-bit histogram bins
#define HSHIFT 19           // key >> 19 = 13-bit prefix

// ---------------- scratch ----------------
__device__ float    g_qpart[4][NE][DIM];   // fully rewritten by kA each run (no init)
__device__ float    g_sim[NE * NB];
__device__ float    g_invnorm[NB];
__device__ unsigned g_h1[NE][HB];          // zeroed at load; re-zeroed by kResolve
__device__ unsigned g_rank[NE];
__device__ int      g_cand[NE][MAXC];
__device__ int      g_ccnt[NE];            // zeroed at load; re-zeroed by kResolve
__device__ unsigned g_thr_key[NE];
__device__ int      g_tiecut[NE];
__device__ float    g_approx[NE][DIM];     // zeroed at load; re-zeroed by kResolve

__device__ __forceinline__ unsigned tokey(float f) {
    unsigned b = __float_as_uint(f);
    return b ^ ((unsigned)((int)b >> 31) | 0x80000000u);
}

// ---------------- A: support mean; each (e,chunk) block owns its qpart slice ----
__global__ void __launch_bounds__(1024) kA(const float* __restrict__ feats) {
    int e = blockIdx.x, chunk = blockIdx.y;
    int tid = threadIdx.x, lane = tid & 31, wid = tid >> 5;
    __shared__ float s_inv[32];
    const float* fe = feats + (size_t)e * DIM * DIM + (size_t)chunk * 32 * DIM;
    {
        const float4* row4 = (const float4*)(fe + (size_t)wid * DIM);
        float s = 0.f;
        #pragma unroll
        for (int k = 0; k < 8; k++) {
            float4 v = row4[k * 32 + lane];
            s += v.x * v.x + v.y * v.y + v.z * v.z + v.w * v.w;
        }
        #pragma unroll
        for (int o = 16; o > 0; o >>= 1) s += __shfl_xor_sync(0xFFFFFFFFu, s, o);
        if (lane == 0) s_inv[wid] = rsqrtf(fmaxf(s, 1e-24f));
    }
    __syncthreads();
    float acc = 0.f;
    #pragma unroll 8
    for (int r = 0; r < 32; r++) acc += fe[(size_t)r * DIM + tid] * s_inv[r];
    g_qpart[chunk][e][tid] = acc;           // direct store — no atomics, no init needed
}

// ---------------- B: sims (FROZEN inner loop); prologue sums the 4 q parts -------
__global__ void __launch_bounds__(128) kB(const float* __restrict__ base) {
    __shared__ float4 sq[NE * 256];   // 32 KB
    {
        const float4* q0 = (const float4*)&g_qpart[0][0][0];
        const float4* q1 = (const float4*)&g_qpart[1][0][0];
        const float4* q2 = (const float4*)&g_qpart[2][0][0];
        const float4* q3 = (const float4*)&g_qpart[3][0][0];
        for (int i = threadIdx.x; i < NE * 256; i += 128) {
            float4 a = q0[i], b = q1[i], c = q2[i], d = q3[i];
            float4 s;
            s.x = (a.x + b.x) + (c.x + d.x);
            s.y = (a.y + b.y) + (c.y + d.y);
            s.z = (a.z + b.z) + (c.z + d.z);
            s.w = (a.w + b.w) + (c.w + d.w);
            sq[i] = s;
        }
    }
    __syncthreads();
    int lane = threadIdx.x & 31;
    int gw = (blockIdx.x * 128 + threadIdx.x) >> 5;
    int nw = (gridDim.x * 128) >> 5;
    for (int g = gw; g < NB / 4; g += nw) {
        const float4* p0 = (const float4*)(base + (size_t)(4 * g) * DIM);
        const float4* p1 = p0 + 256;
        const float4* p2 = p0 + 512;
        const float4* p3 = p0 + 768;
        float acc[4][8];
        float ss[4];
        #pragma unroll
        for (int r = 0; r < 4; r++) {
            ss[r] = 0.f;
            #pragma unroll
            for (int e = 0; e < 8; e++) acc[r][e] = 0.f;
        }
        #pragma unroll 2
        for (int k = 0; k < 8; k++) {
            float4 v0 = p0[k * 32 + lane];
            float4 v1 = p1[k * 32 + lane];
            float4 v2 = p2[k * 32 + lane];
            float4 v3 = p3[k * 32 + lane];
            ss[0] += v0.x * v0.x + v0.y * v0.y + v0.z * v0.z + v0.w * v0.w;
            ss[1] += v1.x * v1.x + v1.y * v1.y + v1.z * v1.z + v1.w * v1.w;
            ss[2] += v2.x * v2.x + v2.y * v2.y + v2.z * v2.z + v2.w * v2.w;
            ss[3] += v3.x * v3.x + v3.y * v3.y + v3.z * v3.z + v3.w * v3.w;
            #pragma unroll
            for (int e = 0; e < 8; e++) {
                float4 q = sq[e * 256 + k * 32 + lane];
                acc[0][e] += v0.x * q.x + v0.y * q.y + v0.z * q.z + v0.w * q.w;
                acc[1][e] += v1.x * q.x + v1.y * q.y + v1.z * q.z + v1.w * q.w;
                acc[2][e] += v2.x * q.x + v2.y * q.y + v2.z * q.z + v2.w * q.w;
                acc[3][e] += v3.x * q.x + v3.y * q.y + v3.z * q.z + v3.w * q.w;
            }
        }
        #pragma unroll
        for (int r = 0; r < 4; r++) {
            float s = ss[r];
            #pragma unroll
            for (int o = 16; o > 0; o >>= 1) s += __shfl_xor_sync(0xFFFFFFFFu, s, o);
            float inv = rsqrtf(fmaxf(s, 1e-24f));
            if (lane == 0) g_invnorm[4 * g + r] = inv;
            #pragma unroll
            for (int e = 0; e < 8; e++) {
                float d = acc[r][e];
                #pragma unroll
                for (int o = 16; o > 0; o >>= 1) d += __shfl_xor_sync(0xFFFFFFFFu, d, o);
                if (lane == 0) g_sim[e * NB + 4 * g + r] = d * inv;
            }
        }
    }
}

// ---------------- H1: 13-bit histogram, float4 sweep ----------------
__global__ void __launch_bounds__(1024) kH1() {
    int e = blockIdx.y;
    __shared__ unsigned h[HB];        // 32 KB
    int t = threadIdx.x;
    #pragma unroll
    for (int j = 0; j < HB / 1024; j++) h[t + j * 1024] = 0u;
    __syncthreads();
    const float4* s4 = (const float4*)(g_sim + (size_t)e * NB);
    int i0 = blockIdx.x * 2048 + t;
    #pragma unroll
    for (int rr = 0; rr < 2; rr++) {
        int i = i0 + rr * 1024;
        if (i < NB / 4) {
            float4 v = s4[i];
            atomicAdd(&h[tokey(v.x) >> HSHIFT], 1u);
            atomicAdd(&h[tokey(v.y) >> HSHIFT], 1u);
            atomicAdd(&h[tokey(v.z) >> HSHIFT], 1u);
            atomicAdd(&h[tokey(v.w) >> HSHIFT], 1u);
        }
    }
    __syncthreads();
    #pragma unroll
    for (int j = 0; j < HB / 1024; j++) {
        unsigned c = h[t + j * 1024];
        if (c) atomicAdd(&g_h1[e][t + j * 1024], c);
    }
}

// ---------------- Cand: in-block find (8192 bins) + float4 collect sweep --------
__global__ void __launch_bounds__(1024) kCand() {
    int e = blockIdx.y;
    int t = threadIdx.x, lane = t & 31, wid = t >> 5;
    __shared__ unsigned s_ws[32];
    __shared__ unsigned s_total;
    __shared__ unsigned s_bin, s_rank;

    // in-block find over g_h1[e] (identical result in every block)
    {
        const unsigned* hist = g_h1[e];
        unsigned base = (unsigned)t * (HB / 1024);
        unsigned hb[8];
        unsigned part = 0;
        #pragma unroll
        for (int j = 0; j < 8; j++) { hb[j] = hist[base + j]; part += hb[j]; }
        unsigned x = part;
        #pragma unroll
        for (int o = 1; o < 32; o <<= 1) { unsigned y = __shfl_up_sync(0xFFFFFFFFu, x, o); if (lane >= o) x += y; }
        if (lane == 31) s_ws[wid] = x;
        __syncthreads();
        if (wid == 0) {
            unsigned w = s_ws[lane];
            #pragma unroll
            for (int o = 1; o < 32; o <<= 1) { unsigned y = __shfl_up_sync(0xFFFFFFFFu, w, o); if (lane >= o) w += y; }
            s_ws[lane] = w;
            if (lane == 31) s_total = w;
        }
        __syncthreads();
        unsigned incl = x + (wid ? s_ws[wid - 1] : 0u);
        unsigned above = s_total - incl;
        if (above < KSEL && KSEL <= above + part) {
            unsigned cum = above;
            for (int j = 7; j >= 0; j--) {
                unsigned c = hb[j];
                if (cum + c >= KSEL) { s_bin = base + j; s_rank = KSEL - cum; break; }
                cum += c;
            }
        }
        __syncthreads();
    }
    if (blockIdx.x == 0 && t == 0) g_rank[e] = s_rank;
    unsigned bin = s_bin;

    const float4* s4 = (const float4*)(g_sim + (size_t)e * NB);
    int i0 = blockIdx.x * 2048 + t;
    #pragma unroll
    for (int rr = 0; rr < 2; rr++) {
        int i = i0 + rr * 1024;
        if (i < NB / 4) {
            float4 v = s4[i];
            float sv[4] = {v.x, v.y, v.z, v.w};
            #pragma unroll
            for (int j = 0; j < 4; j++) {
                if ((tokey(sv[j]) >> HSHIFT) == bin) {
                    int p = atomicAdd(&g_ccnt[e], 1);
                    if (p < MAXC) g_cand[e][p] = 4 * i + j;
                }
            }
        }
    }
}

// ---------------- Resolve v2 + scratch cleanup for next graph replay ------------
__global__ void __launch_bounds__(1024) kResolve() {
    int e = blockIdx.x;
    int cnt = min(g_ccnt[e], MAXC);
    unsigned rank = g_rank[e];
    int t = threadIdx.x;
    const float* sims = g_sim + (size_t)e * NB;
    const int* cand = g_cand[e];

    __shared__ unsigned h[256], sfx[256];
    __shared__ unsigned s_bin, s_rank2;
    __shared__ int s_m;
    __shared__ int midx[1024];
    __shared__ unsigned mkey[1024];
    if (t < 256) { h[t] = 0u; }
    if (t == 0) s_m = 0;
    __syncthreads();
    for (int i = t; i < cnt; i += 1024) {
        unsigned key = tokey(sims[cand[i]]);
        atomicAdd(&h[(key >> 11) & 0xFFu], 1u);
    }
    __syncthreads();
    if (t < 256) sfx[t] = h[t];
    __syncthreads();
    #pragma unroll
    for (int o = 1; o < 256; o <<= 1) {
        unsigned v = 0;
        if (t < 256 && t + o < 256) v = sfx[t + o];
        __syncthreads();
        if (t < 256) sfx[t] += v;
        __syncthreads();
    }
    if (t < 256) {
        unsigned tot = sfx[t], above = tot - h[t];
        if (above < rank && rank <= tot) { s_bin = (unsigned)t; s_rank2 = rank - above; }
    }
    __syncthreads();
    unsigned b = s_bin, rank2 = s_rank2;

    for (int i = t; i < cnt; i += 1024) {
        int idx = cand[i];
        unsigned key = tokey(sims[idx]);
        if (((key >> 11) & 0xFFu) == b) {
            int p = atomicAdd(&s_m, 1);
            if (p < 1024) { midx[p] = idx; mkey[p] = key; }
        }
    }
    __syncthreads();
    int m = min(s_m, 1024);
    for (int i = t; i < m; i += 1024) {
        int my = midx[i]; unsigned myk = mkey[i];
        int r = 0;
        for (int j = 0; j < m; j++) {
            unsigned ok = mkey[j]; int oj = midx[j];
            r += (ok > myk) || (ok == myk && oj < my);
        }
        if (r == (int)rank2 - 1) { g_thr_key[e] = myk; g_tiecut[e] = my; }
    }

    // cleanup for next graph replay (all consumers of these have run)
    #pragma unroll
    for (int j = 0; j < HB / 1024; j++) g_h1[e][t + j * 1024] = 0u;
    g_approx[e][t] = 0.0f;
    if (t == 0) g_ccnt[e] = 0;
}

// ---------------- D: warp-per-episode sparse weighted accumulation ----------------
__global__ void __launch_bounds__(256) kD(const float* __restrict__ base) {
    int e = threadIdx.x >> 5;
    int lane = threadIdx.x & 31;
    unsigned thr = g_thr_key[e];
    int cut = g_tiecut[e];
    const float* sims = g_sim + (size_t)e * NB;
    const float4* b4 = (const float4*)base;
    float4 acc[8];
    #pragma unroll
    for (int i = 0; i < 8; i++) acc[i] = make_float4(0.f, 0.f, 0.f, 0.f);
    for (int tile = blockIdx.x; tile < NB / 16; tile += gridDim.x) {
        int row0 = tile * 16;
        float w = 0.f;
        if (lane < 16) {
            int row = row0 + lane;
            float sim = sims[row];
            unsigned key = tokey(sim);
            bool sel = (key > thr) || (key == thr && row <= cut);
            w = sel ? (sqrtf(fmaxf(sim, 0.f)) * g_invnorm[row]) : 0.f;
        }
        unsigned mask = __ballot_sync(0xFFFFFFFFu, w != 0.f);
        while (mask) {
            int r = __ffs(mask) - 1; mask &= mask - 1;
            float wr = __shfl_sync(0xFFFFFFFFu, w, r);
            const float4* rp = b4 + (size_t)(row0 + r) * 256;
            #pragma unroll
            for (int i = 0; i < 8; i++) {
                float4 v = rp[i * 32 + lane];
                acc[i].x += wr * v.x; acc[i].y += wr * v.y;
                acc[i].z += wr * v.z; acc[i].w += wr * v.w;
            }
        }
    }
    #pragma unroll
    for (int i = 0; i < 8; i++) {
        int c = (i * 32 + lane) * 4;
        atomicAdd(&g_approx[e][c + 0], acc[i].x);
        atomicAdd(&g_approx[e][c + 1], acc[i].y);
        atomicAdd(&g_approx[e][c + 2], acc[i].z);
        atomicAdd(&g_approx[e][c + 3], acc[i].w);
    }
}

// ---------------- F: orthogonalize (approx normalization fused in) ----------------
__global__ void __launch_bounds__(256) kF(const float* __restrict__ feats, float* __restrict__ out) {
    int b = blockIdx.x;
    int e = b >> 7;
    int tid = threadIdx.x;
    int lane = tid & 31, warp = tid >> 5;

    __shared__ float s_part[8];
    __shared__ float s_inva;
    const float4* a4 = (const float4*)g_approx[e];
    {
        float4 av = a4[tid];
        float ss = av.x * av.x + av.y * av.y + av.z * av.z + av.w * av.w;
        #pragma unroll
        for (int o = 16; o > 0; o >>= 1) ss += __shfl_xor_sync(0xFFFFFFFFu, ss, o);
        if (lane == 0) s_part[warp] = ss;
    }
    __syncthreads();
    if (tid == 0) {
        float tsum = 0.f;
        #pragma unroll
        for (int i = 0; i < 8; i++) tsum += s_part[i];
        s_inva = rsqrtf(fmaxf(tsum, 1e-24f));
    }
    __syncthreads();
    float inva = s_inva;

    int rowInEp = (b & 127) * 8 + warp;
    size_t off = ((size_t)e * DIM + rowInEp) * DIM;
    const float4* f4 = (const float4*)(feats + off);
    float4* o4 = (float4*)(out + off);
    float4 v[8], a[8];
    float ss = 0.f, dd = 0.f;
    #pragma unroll
    for (int k = 0; k < 8; k++) {
        v[k] = f4[k * 32 + lane];
        a[k] = a4[k * 32 + lane];
        ss += v[k].x * v[k].x + v[k].y * v[k].y + v[k].z * v[k].z + v[k].w * v[k].w;
        dd += v[k].x * a[k].x + v[k].y * a[k].y + v[k].z * a[k].z + v[k].w * a[k].w;
    }
    #pragma unroll
    for (int o = 16; o > 0; o >>= 1) {
        ss += __shfl_xor_sync(0xFFFFFFFFu, ss, o);
        dd += __shfl_xor_sync(0xFFFFFFFFu, dd, o);
    }
    float invf = rsqrtf(fmaxf(ss, 1e-24f));
    float c = dd * invf * inva;
    float tcoef = c * inva;
    float sc = rsqrtf(fmaxf(1.0f - c * c, 1e-24f));
    #pragma unroll
    for (int k = 0; k < 8; k++) {
        float4 r;
        r.x = (v[k].x * invf - tcoef * a[k].x) * sc;
        r.y = (v[k].y * invf - tcoef * a[k].y) * sc;
        r.z = (v[k].z * invf - tcoef * a[k].z) * sc;
        r.w = (v[k].w * invf - tcoef * a[k].w) * sc;
        o4[k * 32 + lane] = r;
    }
}

// ---------------- launch (7 kernels) ----------------
extern "C" void kernel_launch(void* const* d_in, const int* in_sizes, int n_in,
                              void* d_out, int out_size) {
    const float* feats = (const float*)d_in[0];
    const float* base  = (const float*)d_in[1];
    float* out = (float*)d_out;
    (void)in_sizes; (void)n_in; (void)out_size;

    kA<<<dim3(NE, 4), 1024>>>(feats);
    kB<<<1480, 128>>>(base);
    kH1<<<dim3(13, NE), 1024>>>();
    kCand<<<dim3(13, NE), 1024>>>();
    kResolve<<<NE, 1024>>>();
    kD<<<592, 256>>>(base);
    kF<<<1024, 256>>>(feats, out);
}